// round 16
// baseline (speedup 1.0000x reference)
#include <cuda_runtime.h>
#include <cuda_fp16.h>

#define B 8192
#define T 15
#define D 81
#define HE 256
#define NG 1024
#define XP 96         // padded x-width for encoder
#define KENC_PAD 352  // 96 (x, padded) + 256 (h)
#define KDEC_PAD 256  // 256 (d); y handled in epilogue

#define BM 128
#define BN 128
#define BK 16
#define NSTG 4
#define ASTG 1040     // per-stage A words: 8 mt * 128 + 16 pad
#define BSTG 1040     // per-stage B words (lstm): 1024 + 16 pad
#define BSTG2 528     // per-stage B words (gemm256): 512 + 16 pad

// ---------------- scratch (static device memory; no allocations) ----------
__device__ __half g_Xs16[T * B * XP];           // [t][b][96] a1*a2-scaled, padded, fp16
__device__ __half g_Wenc16[KENC_PAD * NG];      // fragment-packed fp16 (layer-2 only)
__device__ float  g_benc[NG];
__device__ __half g_Wdec16[KDEC_PAD * NG];
__device__ float  g_bdec[NG];
__device__ float  g_wyt[NG];                    // packed dl_wih (y contribution)
__device__ __half g_Wq16[512 * HE];             // k<256 -> W1d, else W1c
__device__ __half g_Wxp16[HE * HE];             // [k][n] = W1x[n][k]
__device__ __half g_h16[2][B * HE];             // [parity] encoder (layer-2) h fp16
__device__ float  g_c2[2][B * HE];
__device__ __half g_Xenc16[B * T * HE];         // fp16 (xproj GEMM A + attention ctx)
__device__ __half g_xproj16[B * T * HE];
__device__ float  g_dc[2][B * 512];             // decoder state [d | c] fp32
__device__ __half g_dc16[2][B * 512];           // fp16 copy for GEMM A
__device__ float  g_q[B * HE];
__device__ __half g_yt16[B];
__device__ float  g_ctx[B * HE];

// ---------------- math helpers -------------------------------------------
__device__ __forceinline__ float sigf(float x) {
    return __fdividef(1.f, 1.f + __expf(-x));
}
__device__ __forceinline__ float ftanh(float x) {
    float e = __expf(-2.f * fabsf(x));
    float r = __fdividef(1.f - e, 1.f + e);
    return copysignf(r, x);
}
__device__ __forceinline__ void mma_f16(float* c, const int4& a, const int2& b) {
    asm volatile(
        "mma.sync.aligned.m16n8k16.row.col.f32.f16.f16.f32 "
        "{%0,%1,%2,%3}, {%4,%5,%6,%7}, {%8,%9}, {%0,%1,%2,%3};\n"
        : "+f"(c[0]), "+f"(c[1]), "+f"(c[2]), "+f"(c[3])
        : "r"(a.x), "r"(a.y), "r"(a.z), "r"(a.w), "r"(b.x), "r"(b.y));
}
__device__ __forceinline__ void cp4(unsigned* smem_dst, const void* gsrc) {
    unsigned d = (unsigned)__cvta_generic_to_shared(smem_dst);
    asm volatile("cp.async.ca.shared.global [%0], [%1], 4;\n" :: "r"(d), "l"(gsrc));
}
__device__ __forceinline__ void cp8(unsigned* smem_dst, const void* gsrc) {
    unsigned d = (unsigned)__cvta_generic_to_shared(smem_dst);
    asm volatile("cp.async.ca.shared.global [%0], [%1], 8;\n" :: "r"(d), "l"(gsrc));
}
__device__ __forceinline__ void cp16(unsigned* smem_dst, const void* gsrc) {
    unsigned d = (unsigned)__cvta_generic_to_shared(smem_dst);
    asm volatile("cp.async.cg.shared.global [%0], [%1], 16;\n" :: "r"(d), "l"(gsrc));
}
#define CP_COMMIT() asm volatile("cp.async.commit_group;\n" ::: "memory")
template <int N>
__device__ __forceinline__ void cp_wait() {
    asm volatile("cp.async.wait_group %0;\n" :: "n"(N) : "memory");
}

// Fragment-packed fp16 B-weight index for m16n8k16.
__device__ __forceinline__ size_t frag16_idx(int k, int c, int ncg) {
    int block = (k >> 4) * ncg + (c >> 6);
    int nt = (c & 63) >> 3;
    int lane = ((c & 7) << 2) + ((k >> 1) & 3);
    int khalf = (k >> 3) & 1, p = k & 1;
    return (size_t)block * 1024 + nt * 128 + lane * 4 + khalf * 2 + p;
}

// Packed column mapping for LSTM weights (col -> original row n)
__device__ __forceinline__ int lstm_src_n(int c) {
    int g32 = c >> 5, p = c & 31;
    int u = (g32 << 3) + ((p & 15) >> 1);
    int gate = ((p & 16) ? 2 : 0) + (p & 1);
    return gate * HE + u;
}

// ---------------- weight packing ------------------------------------------
__global__ void pack_kernel(const float* __restrict__ l2_wih, const float* __restrict__ l2_whh,
                            const float* __restrict__ l2_b,
                            const float* __restrict__ dl_wih, const float* __restrict__ dl_whh,
                            const float* __restrict__ dl_b,
                            const float* __restrict__ da1w) {
    int stride = gridDim.x * blockDim.x;
    int idx0 = blockIdx.x * blockDim.x + threadIdx.x;
    for (int i = idx0; i < KENC_PAD * NG; i += stride) {
        int k = i >> 10, col = i & 1023;
        int n = lstm_src_n(col);
        float v = 0.f;
        if (k < D)        v = l2_wih[n * D + k];
        else if (k >= XP) v = l2_whh[n * HE + (k - XP)];
        g_Wenc16[frag16_idx(k, col, 16)] = __float2half_rn(v);
    }
    for (int i = idx0; i < KDEC_PAD * NG; i += stride) {
        int k = i >> 10, col = i & 1023;
        int n = lstm_src_n(col);
        g_Wdec16[frag16_idx(k, col, 16)] = __float2half_rn(dl_whh[n * HE + k]);
    }
    for (int i = idx0; i < 512 * HE; i += stride) {
        int k = i >> 8, n = i & 255;
        float v = (k < HE) ? da1w[n * 768 + k] : da1w[n * 768 + 256 + (k - HE)];
        g_Wq16[frag16_idx(k, n, 4)] = __float2half_rn(v);
    }
    for (int i = idx0; i < HE * HE; i += stride) {
        int k = i >> 8, n = i & 255;
        g_Wxp16[frag16_idx(k, n, 4)] = __float2half_rn(da1w[n * 768 + 512 + k]);
    }
    for (int i = idx0; i < NG; i += stride) {
        int n = lstm_src_n(i);
        g_benc[i] = l2_b[n];
        g_bdec[i] = dl_b[n];
        g_wyt[i]  = dl_wih[n];
    }
}

__global__ void init_kernel() {
    int stride = gridDim.x * blockDim.x;
    int i0 = blockIdx.x * blockDim.x + threadIdx.x;
    __half hz = __float2half_rn(0.f);
    for (int j = i0; j < B * HE; j += stride) {
        g_h16[0][j] = hz;
        g_c2[0][j] = 0.f;
    }
    for (int j = i0; j < B * 512; j += stride) {
        g_dc[0][j] = 0.f;
        g_dc16[0][j] = hz;
    }
}

// ------- input attention (a1*a2) + fused scaled-X production --------------
__global__ void attn_kernel(const float* __restrict__ X, const float* __restrict__ yprev,
                            const float* __restrict__ e1w, const float* __restrict__ e1b,
                            const float* __restrict__ e2w, const float* __restrict__ e2b) {
    int b = blockIdx.x;
    int j = threadIdx.x;
    float v1 = -1e30f, v2 = -1e30f;
    float xv[T];
    if (j < D) {
        const float* xb = X + (size_t)b * T * D + j;
        float s1 = 0.f, s2 = 0.f;
#pragma unroll
        for (int t = 0; t < T; ++t) {
            float x = xb[t * D];
            xv[t] = x;
            s1 += x * e1w[2 * HE + t];
            s2 += x * e2w[2 * HE + t];
        }
        float yw = 0.f;
#pragma unroll
        for (int t = 0; t < T; ++t) yw += yprev[b * T + t] * e2w[2 * HE + T + t];
        v1 = s1 + e1b[0];
        v2 = s2 + yw + e2b[0];
    }
    __shared__ float red1[128], red2[128];
    red1[j] = v1; red2[j] = v2;
    __syncthreads();
    for (int o = 64; o > 0; o >>= 1) {
        if (j < o) {
            red1[j] = fmaxf(red1[j], red1[j + o]);
            red2[j] = fmaxf(red2[j], red2[j + o]);
        }
        __syncthreads();
    }
    float m1 = red1[0], m2 = red2[0];
    __syncthreads();
    float e1v = (j < D) ? __expf(v1 - m1) : 0.f;
    float e2v = (j < D) ? __expf(v2 - m2) : 0.f;
    red1[j] = e1v; red2[j] = e2v;
    __syncthreads();
    for (int o = 64; o > 0; o >>= 1) {
        if (j < o) { red1[j] += red1[j + o]; red2[j] += red2[j + o]; }
        __syncthreads();
    }
    float a12 = 0.f;
    if (j < D)
        a12 = __fdividef(e1v, red1[0]) * __fdividef(e2v, red2[0]);
    if (j < XP) {
        __half hz = __float2half_rn(0.f);
#pragma unroll
        for (int t = 0; t < T; ++t) {
            __half val = (j < D) ? __float2half_rn(a12 * xv[t]) : hz;
            g_Xs16[(size_t)t * B * XP + b * XP + j] = val;
        }
    }
}

// ============= fp16 tensor-core GEMM + fused LSTM epilogue =================
// MODE 0: encoder step (layer 2 only); MODE 1: decoder LSTM
template <int MODE>
__global__ __launch_bounds__(256) void lstm_mma_kernel(int t, int pin, int pout) {
    const __half* xsrc = nullptr;
    const __half* h16in = nullptr;
    const float* cin = nullptr;
    __half* h16out = nullptr;
    float* cout = nullptr;
    const __half* Wg;
    const float* bias;
    const float* dcin = nullptr;
    float* dcout = nullptr;
    const __half* d16in = nullptr;
    __half* d16out = nullptr;
    int NC;
    if (MODE == 0) {
        xsrc = &g_Xs16[(size_t)t * B * XP];
        h16in = g_h16[pin];
        h16out = g_h16[pout];
        cin = g_c2[pin];
        cout = g_c2[pout];
        Wg = g_Wenc16;
        bias = g_benc;
        NC = KENC_PAD / BK;      // 22
    } else {
        dcin = g_dc[pin];
        dcout = g_dc[pout];
        d16in = g_dc16[pin];
        d16out = g_dc16[pout];
        Wg = g_Wdec16;
        bias = g_bdec;
        NC = KDEC_PAD / BK;      // 16
    }

    __shared__ __align__(16) unsigned Asw[NSTG * ASTG];
    __shared__ __align__(16) unsigned Bsw[NSTG * BSTG];

    int tid = threadIdx.x;
    int lane = tid & 31;
    int wid = tid >> 5;
    int wm = wid & 3, wn = wid >> 2;      // 4 row-warps x 2 col-warps (64 cols each)
    int lq = lane & 3, lr = lane >> 2;
    int row0 = blockIdx.x * BM;
    int col0 = blockIdx.y * BN;
    int cg = col0 >> 6;

    // A loader: thread = (row, k-half); scatters 4 x 4B into fragment layout
    int arow = tid >> 1;
    int akf = tid & 1;
    int agb = row0 + arow;
    int rt = arow & 15, mt = arow >> 4;
    int r = rt & 7, rhalf = rt >> 3;
    int abase = mt * 128 + akf * 2 + rhalf;

    const __half* xrow = (MODE == 0) ? (xsrc + (size_t)agb * XP) : nullptr;
    const __half* hrow = (MODE == 0) ? (h16in + (size_t)agb * HE) : (d16in + (size_t)agb * 512);
    const int4* wp4 = reinterpret_cast<const int4*>(Wg);

    float acc[2][8][4] = {};

    auto issueStage = [&](int kc) {
        int stg = kc & (NSTG - 1);
        unsigned* as = &Asw[stg * ASTG];
        const __half* p;
        if (MODE == 0)
            p = (kc < 6) ? (xrow + kc * 16 + akf * 8) : (hrow + (kc - 6) * 16 + akf * 8);
        else
            p = hrow + kc * 16 + akf * 8;
#pragma unroll
        for (int j2 = 0; j2 < 4; ++j2)
            cp4(&as[abase + ((r * 4 + (j2 ^ (r >> 1))) << 2)], p + j2 * 2);
        cp16(&Bsw[stg * BSTG + tid * 4], wp4 + (((size_t)(kc * 16 + cg)) << 7) + tid);
    };
    auto compute = [&](int stg) {
        const unsigned* as = &Asw[stg * ASTG];
        const unsigned* bs = &Bsw[stg * BSTG];
        int aoff = (lr * 4 + (lq ^ (lr >> 1))) * 4;
        int4 af[2];
        int2 bf[8];
#pragma unroll
        for (int mi = 0; mi < 2; ++mi)
            af[mi] = *(const int4*)&as[(wm * 2 + mi) * 128 + aoff];
#pragma unroll
        for (int ni = 0; ni < 8; ++ni)
            bf[ni] = *(const int2*)&bs[(wn * 8 + ni) * 64 + lane * 2];
#pragma unroll
        for (int mi = 0; mi < 2; ++mi)
#pragma unroll
            for (int ni = 0; ni < 8; ++ni)
                mma_f16(acc[mi][ni], af[mi], bf[ni]);
    };

#pragma unroll
    for (int s = 0; s < NSTG - 1; ++s) {
        issueStage(s);
        CP_COMMIT();
    }
#pragma unroll 1
    for (int kc = 0; kc < NC; ++kc) {
        cp_wait<NSTG - 2>();
        __syncthreads();
        int ks = kc + NSTG - 1;
        if (ks < NC) issueStage(ks);
        CP_COMMIT();
        compute(kc & (NSTG - 1));
    }

    // ---- fused LSTM epilogue on gate-interleaved columns ----
#pragma unroll
    for (int g32 = 0; g32 < 2; ++g32) {
        int cbase = col0 + wn * 64 + g32 * 32;
#pragma unroll
        for (int upair = 0; upair < 2; ++upair) {
            int unit = (cbase >> 2) + upair * 4 + lq;
            float bI = bias[cbase + upair * 8 + 2 * lq];
            float bF = bias[cbase + upair * 8 + 2 * lq + 1];
            float bG = bias[cbase + 16 + upair * 8 + 2 * lq];
            float bO = bias[cbase + 16 + upair * 8 + 2 * lq + 1];
            float wI = 0.f, wF = 0.f, wG = 0.f, wO = 0.f;
            if (MODE == 1) {
                wI = g_wyt[cbase + upair * 8 + 2 * lq];
                wF = g_wyt[cbase + upair * 8 + 2 * lq + 1];
                wG = g_wyt[cbase + 16 + upair * 8 + 2 * lq];
                wO = g_wyt[cbase + 16 + upair * 8 + 2 * lq + 1];
            }
            int niI = g32 * 4 + upair;      // i/f accumulator
            int niG = g32 * 4 + 2 + upair;  // g/o accumulator
#pragma unroll
            for (int mi = 0; mi < 2; ++mi) {
#pragma unroll
                for (int half = 0; half < 2; ++half) {
                    int gb = row0 + wm * 32 + mi * 16 + half * 8 + lr;
                    float gi = acc[mi][niI][half * 2 + 0] + bI;
                    float gf = acc[mi][niI][half * 2 + 1] + bF;
                    float gg = acc[mi][niG][half * 2 + 0] + bG;
                    float go = acc[mi][niG][half * 2 + 1] + bO;
                    float cold;
                    if (MODE == 0) {
                        cold = cin[gb * HE + unit];
                    } else {
                        float yv = __half2float(g_yt16[gb]);
                        gi += yv * wI; gf += yv * wF; gg += yv * wG; go += yv * wO;
                        cold = dcin[gb * 512 + 256 + unit];
                    }
                    float c2 = sigf(gf) * cold + sigf(gi) * ftanh(gg);
                    float h2 = sigf(go) * ftanh(c2);
                    if (MODE == 0) {
                        h16out[gb * HE + unit] = __float2half_rn(h2);
                        cout[gb * HE + unit] = c2;
                        g_Xenc16[((size_t)gb * T + t) * HE + unit] = __float2half_rn(h2);
                    } else {
                        dcout[gb * 512 + unit] = h2;
                        dcout[gb * 512 + 256 + unit] = c2;
                        d16out[gb * 512 + unit] = __float2half_rn(h2);
                        d16out[gb * 512 + 256 + unit] = __float2half_rn(c2);
                    }
                }
            }
        }
    }
}

// ---------------- fp16 plain GEMM, N=256 (xenc_proj and q) ----------------
// mode 0: xproj16 = Xenc @ Wxp + da1b  (M = B*T, K = 256), fp16 out
// mode 1: q       = [d|c] @ Wq         (M = B,   K = 512), fp32 out
__global__ __launch_bounds__(256) void gemm256_mma_kernel(int mode, int pin,
                                                          const float* __restrict__ bias) {
    const __half* Aptr;
    const __half* Wptr;
    int lda, NC;
    if (mode == 0) { Aptr = g_Xenc16;    Wptr = g_Wxp16; lda = 256; NC = 16; }
    else           { Aptr = g_dc16[pin]; Wptr = g_Wq16;  lda = 512; NC = 32; }

    __shared__ __align__(16) unsigned Asw[NSTG * ASTG];
    __shared__ __align__(16) unsigned Bsw[NSTG * BSTG2];

    int tid = threadIdx.x;
    int lane = tid & 31;
    int wid = tid >> 5;
    int wm = wid & 3, wn = wid >> 2;
    int lq = lane & 3, lr = lane >> 2;
    int row0 = blockIdx.x * BM;
    int col0 = blockIdx.y * 64;
    int cg = col0 >> 6;

    int arow = tid >> 1;
    int akf = tid & 1;
    int rt = arow & 15, mt = arow >> 4;
    int r = rt & 7, rhalf = rt >> 3;
    int abase = mt * 128 + akf * 2 + rhalf;
    const __half* arowp = Aptr + (size_t)(row0 + arow) * lda + akf * 8;
    const int2* wp = reinterpret_cast<const int2*>(Wptr);

    float acc[2][4][4] = {};

    auto issueStage = [&](int kc) {
        int stg = kc & (NSTG - 1);
        unsigned* as = &Asw[stg * ASTG];
        const __half* p = arowp + kc * 16;
#pragma unroll
        for (int j2 = 0; j2 < 4; ++j2)
            cp4(&as[abase + ((r * 4 + (j2 ^ (r >> 1))) << 2)], p + j2 * 2);
        cp8(&Bsw[stg * BSTG2 + tid * 2], wp + (((size_t)(kc * 4 + cg)) << 8) + tid);
    };
    auto compute = [&](int stg) {
        const unsigned* as = &Asw[stg * ASTG];
        const unsigned* bs = &Bsw[stg * BSTG2];
        int aoff = (lr * 4 + (lq ^ (lr >> 1))) * 4;
        int4 af[2];
        int2 bf[4];
#pragma unroll
        for (int mi = 0; mi < 2; ++mi)
            af[mi] = *(const int4*)&as[(wm * 2 + mi) * 128 + aoff];
#pragma unroll
        for (int ni = 0; ni < 4; ++ni)
            bf[ni] = *(const int2*)&bs[(wn * 4 + ni) * 64 + lane * 2];
#pragma unroll
        for (int mi = 0; mi < 2; ++mi)
#pragma unroll
            for (int ni = 0; ni < 4; ++ni)
                mma_f16(acc[mi][ni], af[mi], bf[ni]);
    };

#pragma unroll
    for (int s = 0; s < NSTG - 1; ++s) {
        issueStage(s);
        CP_COMMIT();
    }
#pragma unroll 1
    for (int kc = 0; kc < NC; ++kc) {
        cp_wait<NSTG - 2>();
        __syncthreads();
        int ks = kc + NSTG - 1;
        if (ks < NC) issueStage(ks);
        CP_COMMIT();
        compute(kc & (NSTG - 1));
    }

#pragma unroll
    for (int mi = 0; mi < 2; ++mi) {
#pragma unroll
        for (int half = 0; half < 2; ++half) {
            int gb = row0 + wm * 32 + mi * 16 + half * 8 + lr;
#pragma unroll
            for (int ni = 0; ni < 4; ++ni) {
                int col = col0 + wn * 32 + ni * 8 + 2 * lq;
                float v0 = acc[mi][ni][half * 2 + 0] + (bias ? bias[col] : 0.f);
                float v1 = acc[mi][ni][half * 2 + 1] + (bias ? bias[col + 1] : 0.f);
                if (mode == 0) {
                    __half2 hv = __floats2half2_rn(v0, v1);
                    *(__half2*)&g_xproj16[(size_t)gb * HE + col] = hv;
                } else {
                    *(float2*)&g_q[(size_t)gb * HE + col] = make_float2(v0, v1);
                }
            }
        }
    }
}

// ---------------- decoder attention (row-wise fused, fp16 streams) --------
__global__ __launch_bounds__(256) void dec_attn_kernel(const float* __restrict__ yprev,
                                                       const float* __restrict__ a2w,
                                                       const float* __restrict__ a2b,
                                                       const float* __restrict__ fcw,
                                                       const float* __restrict__ fcb, int t) {
    int b = blockIdx.x;
    int h = threadIdx.x;
    float qh = g_q[b * HE + h];
    float w = a2w[h];
    const __half* xp = g_xproj16 + (size_t)(b * T) * HE + h;
    float sloc[T];
#pragma unroll
    for (int tt = 0; tt < T; ++tt)
        sloc[tt] = ftanh(__half2float(xp[tt * HE]) + qh) * w;

    __shared__ float part[8][T];
    __shared__ float beta[T];
    int lane = h & 31, wid = h >> 5;
#pragma unroll
    for (int tt = 0; tt < T; ++tt) {
        float v = sloc[tt];
        for (int o = 16; o > 0; o >>= 1) v += __shfl_down_sync(0xFFFFFFFFu, v, o);
        if (!lane) part[wid][tt] = v;
    }
    __syncthreads();
    if (h == 0) {
        float sc[T];
        float mx = -1e30f;
#pragma unroll
        for (int tt = 0; tt < T; ++tt) {
            float s = a2b[0];
#pragma unroll
            for (int w8 = 0; w8 < 8; ++w8) s += part[w8][tt];
            sc[tt] = s;
            mx = fmaxf(mx, s);
        }
        float sum = 0.f;
#pragma unroll
        for (int tt = 0; tt < T; ++tt) { sc[tt] = __expf(sc[tt] - mx); sum += sc[tt]; }
        float inv = __fdividef(1.f, sum);
#pragma unroll
        for (int tt = 0; tt < T; ++tt) beta[tt] = sc[tt] * inv;
    }
    __syncthreads();
    const __half* xe = g_Xenc16 + (size_t)(b * T) * HE + h;
    float ctx = 0.f;
#pragma unroll
    for (int tt = 0; tt < T; ++tt) ctx += beta[tt] * __half2float(xe[tt * HE]);
    g_ctx[b * HE + h] = ctx;
    float yv = ctx * fcw[h];
    for (int o = 16; o > 0; o >>= 1) yv += __shfl_down_sync(0xFFFFFFFFu, yv, o);
    __syncthreads();
    if (!lane) part[wid][0] = yv;
    __syncthreads();
    if (h == 0) {
        float s = 0.f;
#pragma unroll
        for (int w8 = 0; w8 < 8; ++w8) s += part[w8][0];
        g_yt16[b] = __float2half_rn(s + yprev[b * T + t] * fcw[HE] + fcb[0]);
    }
}

// ---------------- final output --------------------------------------------
__global__ void final_kernel(const float* __restrict__ ffw, const float* __restrict__ ffb,
                             float* __restrict__ out, int pin) {
    int gtid = blockIdx.x * blockDim.x + threadIdx.x;
    int warp = gtid >> 5;
    int lane = gtid & 31;
    if (warp >= B) return;
    const float* d = g_dc[pin] + warp * 512;
    const float* ctx = g_ctx + warp * HE;
    float s = 0.f;
    for (int h = lane; h < HE; h += 32) s += d[h] * ffw[h] + ctx[h] * ffw[HE + h];
    for (int o = 16; o > 0; o >>= 1) s += __shfl_down_sync(0xFFFFFFFFu, s, o);
    if (!lane) out[warp] = s + ffb[0];
}

// ---------------- launch ---------------------------------------------------
extern "C" void kernel_launch(void* const* d_in, const int* in_sizes, int n_in,
                              void* d_out, int out_size) {
    const float* X      = (const float*)d_in[0];
    const float* yprev  = (const float*)d_in[1];
    const float* e1w    = (const float*)d_in[2];
    const float* e1b    = (const float*)d_in[3];
    const float* e2w    = (const float*)d_in[4];
    const float* e2b    = (const float*)d_in[5];
    const float* l2_wih = (const float*)d_in[9];
    const float* l2_whh = (const float*)d_in[10];
    const float* l2_b   = (const float*)d_in[11];
    const float* da1w   = (const float*)d_in[12];
    const float* da1b   = (const float*)d_in[13];
    const float* da2w   = (const float*)d_in[14];
    const float* da2b   = (const float*)d_in[15];
    const float* dlwih  = (const float*)d_in[16];
    const float* dlwhh  = (const float*)d_in[17];
    const float* dlb    = (const float*)d_in[18];
    const float* fcw    = (const float*)d_in[19];
    const float* fcb    = (const float*)d_in[20];
    const float* ffw    = (const float*)d_in[21];
    const float* ffb    = (const float*)d_in[22];
    float* out = (float*)d_out;

    pack_kernel<<<512, 256>>>(l2_wih, l2_whh, l2_b, dlwih, dlwhh, dlb, da1w);
    init_kernel<<<512, 256>>>();
    attn_kernel<<<B, 128>>>(X, yprev, e1w, e1b, e2w, e2b);

    for (int t = 0; t < T; ++t)
        lstm_mma_kernel<0><<<dim3(B / BM, NG / BN), 256>>>(t, t & 1, (t + 1) & 1);

    // xenc_proj over all (b, t)
    gemm256_mma_kernel<<<dim3(B * T / BM, HE / 64), 256>>>(0, 0, da1b);

    for (int t = 0; t < T; ++t) {
        gemm256_mma_kernel<<<dim3(B / BM, HE / 64), 256>>>(1, t & 1, nullptr);
        dec_attn_kernel<<<B, 256>>>(yprev, da2w, da2b, fcw, fcb, t);
        lstm_mma_kernel<1><<<dim3(B / BM, NG / BN), 256>>>(0, t & 1, (t + 1) & 1);
    }

    final_kernel<<<B * 32 / 256, 256>>>(ffw, ffb, out, T & 1);
}

// round 17
// speedup vs baseline: 1.2555x; 1.2555x over previous
#include <cuda_runtime.h>
#include <cuda_fp16.h>

#define B 8192
#define T 15
#define D 81
#define HE 256
#define NG 1024
#define XP 96         // padded x-width for encoder
#define KENC_PAD 352  // 96 (x, padded) + 256 (h) = 11 * 32
#define KDEC_PAD 256  // 256 (d) = 8 * 32; y handled in epilogue

#define BM 128
#define BN 128
#define BK 32
#define AG 1040       // per-k-group A words: 8 mt * 128 + 16 pad
#define BG 1040       // per-k-group B words (lstm, 2 cg): 1024 + 16 pad
#define BG2 528       // per-k-group B words (gemm256, 1 cg): 512 + 16 pad

// ---------------- scratch (static device memory; no allocations) ----------
__device__ __half g_Xs16[T * B * XP];           // [t][b][96] a1*a2-scaled, padded, fp16
__device__ __half g_Wenc16[KENC_PAD * NG];      // fragment-packed fp16 (layer-2 only)
__device__ float  g_benc[NG];
__device__ __half g_Wdec16[KDEC_PAD * NG];
__device__ float  g_bdec[NG];
__device__ float  g_wyt[NG];                    // packed dl_wih (y contribution)
__device__ __half g_Wq16[512 * HE];             // k<256 -> W1d, else W1c
__device__ __half g_Wxp16[HE * HE];             // [k][n] = W1x[n][k]
__device__ __half g_h16[2][B * HE];             // [parity] encoder (layer-2) h fp16
__device__ float  g_c2[2][B * HE];
__device__ __half g_Xenc16[B * T * HE];         // fp16 (xproj GEMM A + attention ctx)
__device__ __half g_xproj16[B * T * HE];
__device__ float  g_dc[2][B * 512];             // decoder state [d | c] fp32
__device__ __half g_dc16[2][B * 512];           // fp16 copy for GEMM A
__device__ float  g_q[B * HE];
__device__ __half g_yt16[B];
__device__ float  g_ctx[B * HE];

// ---------------- math helpers -------------------------------------------
__device__ __forceinline__ float sigf(float x) {
    return __fdividef(1.f, 1.f + __expf(-x));
}
__device__ __forceinline__ float ftanh(float x) {
    float e = __expf(-2.f * fabsf(x));
    float r = __fdividef(1.f - e, 1.f + e);
    return copysignf(r, x);
}
__device__ __forceinline__ void mma_f16(float* c, const int4& a, const int2& b) {
    asm volatile(
        "mma.sync.aligned.m16n8k16.row.col.f32.f16.f16.f32 "
        "{%0,%1,%2,%3}, {%4,%5,%6,%7}, {%8,%9}, {%0,%1,%2,%3};\n"
        : "+f"(c[0]), "+f"(c[1]), "+f"(c[2]), "+f"(c[3])
        : "r"(a.x), "r"(a.y), "r"(a.z), "r"(a.w), "r"(b.x), "r"(b.y));
}

// Fragment-packed fp16 B-weight index for m16n8k16.
__device__ __forceinline__ size_t frag16_idx(int k, int c, int ncg) {
    int block = (k >> 4) * ncg + (c >> 6);
    int nt = (c & 63) >> 3;
    int lane = ((c & 7) << 2) + ((k >> 1) & 3);
    int khalf = (k >> 3) & 1, p = k & 1;
    return (size_t)block * 1024 + nt * 128 + lane * 4 + khalf * 2 + p;
}

// Packed column mapping for LSTM weights (col -> original row n)
__device__ __forceinline__ int lstm_src_n(int c) {
    int g32 = c >> 5, p = c & 31;
    int u = (g32 << 3) + ((p & 15) >> 1);
    int gate = ((p & 16) ? 2 : 0) + (p & 1);
    return gate * HE + u;
}

// ---------------- weight packing ------------------------------------------
__global__ void pack_kernel(const float* __restrict__ l2_wih, const float* __restrict__ l2_whh,
                            const float* __restrict__ l2_b,
                            const float* __restrict__ dl_wih, const float* __restrict__ dl_whh,
                            const float* __restrict__ dl_b,
                            const float* __restrict__ da1w) {
    int stride = gridDim.x * blockDim.x;
    int idx0 = blockIdx.x * blockDim.x + threadIdx.x;
    for (int i = idx0; i < KENC_PAD * NG; i += stride) {
        int k = i >> 10, col = i & 1023;
        int n = lstm_src_n(col);
        float v = 0.f;
        if (k < D)        v = l2_wih[n * D + k];
        else if (k >= XP) v = l2_whh[n * HE + (k - XP)];
        g_Wenc16[frag16_idx(k, col, 16)] = __float2half_rn(v);
    }
    for (int i = idx0; i < KDEC_PAD * NG; i += stride) {
        int k = i >> 10, col = i & 1023;
        int n = lstm_src_n(col);
        g_Wdec16[frag16_idx(k, col, 16)] = __float2half_rn(dl_whh[n * HE + k]);
    }
    for (int i = idx0; i < 512 * HE; i += stride) {
        int k = i >> 8, n = i & 255;
        float v = (k < HE) ? da1w[n * 768 + k] : da1w[n * 768 + 256 + (k - HE)];
        g_Wq16[frag16_idx(k, n, 4)] = __float2half_rn(v);
    }
    for (int i = idx0; i < HE * HE; i += stride) {
        int k = i >> 8, n = i & 255;
        g_Wxp16[frag16_idx(k, n, 4)] = __float2half_rn(da1w[n * 768 + 512 + k]);
    }
    for (int i = idx0; i < NG; i += stride) {
        int n = lstm_src_n(i);
        g_benc[i] = l2_b[n];
        g_bdec[i] = dl_b[n];
        g_wyt[i]  = dl_wih[n];
    }
}

__global__ void init_kernel() {
    int stride = gridDim.x * blockDim.x;
    int i0 = blockIdx.x * blockDim.x + threadIdx.x;
    __half hz = __float2half_rn(0.f);
    for (int j = i0; j < B * HE; j += stride) {
        g_h16[0][j] = hz;
        g_c2[0][j] = 0.f;
    }
    for (int j = i0; j < B * 512; j += stride) {
        g_dc[0][j] = 0.f;
        g_dc16[0][j] = hz;
    }
}

// ------- input attention (a1*a2) + fused scaled-X production --------------
__global__ void attn_kernel(const float* __restrict__ X, const float* __restrict__ yprev,
                            const float* __restrict__ e1w, const float* __restrict__ e1b,
                            const float* __restrict__ e2w, const float* __restrict__ e2b) {
    int b = blockIdx.x;
    int j = threadIdx.x;
    float v1 = -1e30f, v2 = -1e30f;
    float xv[T];
    if (j < D) {
        const float* xb = X + (size_t)b * T * D + j;
        float s1 = 0.f, s2 = 0.f;
#pragma unroll
        for (int t = 0; t < T; ++t) {
            float x = xb[t * D];
            xv[t] = x;
            s1 += x * e1w[2 * HE + t];
            s2 += x * e2w[2 * HE + t];
        }
        float yw = 0.f;
#pragma unroll
        for (int t = 0; t < T; ++t) yw += yprev[b * T + t] * e2w[2 * HE + T + t];
        v1 = s1 + e1b[0];
        v2 = s2 + yw + e2b[0];
    }
    __shared__ float red1[128], red2[128];
    red1[j] = v1; red2[j] = v2;
    __syncthreads();
    for (int o = 64; o > 0; o >>= 1) {
        if (j < o) {
            red1[j] = fmaxf(red1[j], red1[j + o]);
            red2[j] = fmaxf(red2[j], red2[j + o]);
        }
        __syncthreads();
    }
    float m1 = red1[0], m2 = red2[0];
    __syncthreads();
    float e1v = (j < D) ? __expf(v1 - m1) : 0.f;
    float e2v = (j < D) ? __expf(v2 - m2) : 0.f;
    red1[j] = e1v; red2[j] = e2v;
    __syncthreads();
    for (int o = 64; o > 0; o >>= 1) {
        if (j < o) { red1[j] += red1[j + o]; red2[j] += red2[j + o]; }
        __syncthreads();
    }
    float a12 = 0.f;
    if (j < D)
        a12 = __fdividef(e1v, red1[0]) * __fdividef(e2v, red2[0]);
    if (j < XP) {
        __half hz = __float2half_rn(0.f);
#pragma unroll
        for (int t = 0; t < T; ++t) {
            __half val = (j < D) ? __float2half_rn(a12 * xv[t]) : hz;
            g_Xs16[(size_t)t * B * XP + b * XP + j] = val;
        }
    }
}

// ============= fp16 tensor-core GEMM + fused LSTM epilogue =================
// MODE 0: encoder step (layer 2 only); MODE 1: decoder LSTM
template <int MODE>
__global__ __launch_bounds__(256) void lstm_mma_kernel(int t, int pin, int pout) {
    const __half* xsrc = nullptr;
    const __half* h16in = nullptr;
    const float* cin = nullptr;
    __half* h16out = nullptr;
    float* cout = nullptr;
    const __half* Wg;
    const float* bias;
    const float* dcin = nullptr;
    float* dcout = nullptr;
    const __half* d16in = nullptr;
    __half* d16out = nullptr;
    int NC;
    if (MODE == 0) {
        xsrc = &g_Xs16[(size_t)t * B * XP];
        h16in = g_h16[pin];
        h16out = g_h16[pout];
        cin = g_c2[pin];
        cout = g_c2[pout];
        Wg = g_Wenc16;
        bias = g_benc;
        NC = KENC_PAD / BK;      // 11
    } else {
        dcin = g_dc[pin];
        dcout = g_dc[pout];
        d16in = g_dc16[pin];
        d16out = g_dc16[pout];
        Wg = g_Wdec16;
        bias = g_bdec;
        NC = KDEC_PAD / BK;      // 8
    }

    __shared__ __align__(16) unsigned Asw[2][2 * AG];
    __shared__ __align__(16) unsigned Bsw[2][2 * BG];

    int tid = threadIdx.x;
    int lane = tid & 31;
    int wid = tid >> 5;
    int wm = wid & 3, wn = wid >> 2;      // 4 row-warps x 2 col-warps (64 cols each)
    int lq = lane & 3, lr = lane >> 2;
    int row0 = blockIdx.x * BM;
    int col0 = blockIdx.y * BN;
    int cg = col0 >> 6;

    // A loader: thread = (row, k-group); loads 16 consecutive halves (2x int4)
    int arow = tid >> 1;
    int akf = tid & 1;                    // k-group (16 k) within BK=32 chunk
    int agb = row0 + arow;
    int rt = arow & 15, mt = arow >> 4;
    int r = rt & 7, rhalf = rt >> 3;
    int abase = akf * AG + mt * 128 + rhalf;

    const __half* xrow = (MODE == 0) ? (xsrc + (size_t)agb * XP + akf * 16) : nullptr;
    const __half* hrow = ((MODE == 0) ? (h16in + (size_t)agb * HE)
                                      : (d16in + (size_t)agb * 512)) + akf * 16;
    const int4* wp4 = reinterpret_cast<const int4*>(Wg);

    float acc[2][8][4] = {};
    int4 av0, av1, bv0, bv1;

    auto loadChunk = [&](int kc) {
        const __half* p;
        if (MODE == 0)
            p = (kc < 3) ? (xrow + kc * 32) : (hrow + (kc - 3) * 32);
        else
            p = hrow + kc * 32;
        av0 = *(const int4*)p;
        av1 = *(const int4*)(p + 8);
        bv0 = wp4[(((size_t)(kc * 2 + 0) * 16 + cg) << 7) + tid];
        bv1 = wp4[(((size_t)(kc * 2 + 1) * 16 + cg) << 7) + tid];
    };
    auto storeChunk = [&](int buf) {
        unsigned v[8] = {(unsigned)av0.x, (unsigned)av0.y, (unsigned)av0.z, (unsigned)av0.w,
                         (unsigned)av1.x, (unsigned)av1.y, (unsigned)av1.z, (unsigned)av1.w};
        unsigned* as = Asw[buf] + abase;
#pragma unroll
        for (int q4 = 0; q4 < 2; ++q4)
#pragma unroll
            for (int j2 = 0; j2 < 4; ++j2)
                as[((r * 4 + (j2 ^ (r >> 1))) << 2) + q4 * 2] = v[q4 * 4 + j2];
        *(int4*)&Bsw[buf][tid * 4] = bv0;
        *(int4*)&Bsw[buf][BG + tid * 4] = bv1;
    };
    auto compute = [&](int buf) {
        int aoff = (lr * 4 + (lq ^ (lr >> 1))) * 4;
#pragma unroll
        for (int kf2 = 0; kf2 < 2; ++kf2) {
            const unsigned* as = &Asw[buf][kf2 * AG];
            const unsigned* bs = &Bsw[buf][kf2 * BG];
            int4 af[2];
            int2 bf[8];
#pragma unroll
            for (int mi = 0; mi < 2; ++mi)
                af[mi] = *(const int4*)&as[(wm * 2 + mi) * 128 + aoff];
#pragma unroll
            for (int ni = 0; ni < 8; ++ni)
                bf[ni] = *(const int2*)&bs[(wn * 8 + ni) * 64 + lane * 2];
#pragma unroll
            for (int mi = 0; mi < 2; ++mi)
#pragma unroll
                for (int ni = 0; ni < 8; ++ni)
                    mma_f16(acc[mi][ni], af[mi], bf[ni]);
        }
    };

    loadChunk(0);
    storeChunk(0);
    __syncthreads();
#pragma unroll 1
    for (int kc = 0; kc < NC; ++kc) {
        int cur = kc & 1;
        if (kc + 1 < NC) loadChunk(kc + 1);
        compute(cur);
        if (kc + 1 < NC) storeChunk(cur ^ 1);
        __syncthreads();
    }

    // ---- fused LSTM epilogue on gate-interleaved columns ----
#pragma unroll
    for (int g32 = 0; g32 < 2; ++g32) {
        int cbase = col0 + wn * 64 + g32 * 32;
#pragma unroll
        for (int upair = 0; upair < 2; ++upair) {
            int unit = (cbase >> 2) + upair * 4 + lq;
            float bI = bias[cbase + upair * 8 + 2 * lq];
            float bF = bias[cbase + upair * 8 + 2 * lq + 1];
            float bG = bias[cbase + 16 + upair * 8 + 2 * lq];
            float bO = bias[cbase + 16 + upair * 8 + 2 * lq + 1];
            float wI = 0.f, wF = 0.f, wG = 0.f, wO = 0.f;
            if (MODE == 1) {
                wI = g_wyt[cbase + upair * 8 + 2 * lq];
                wF = g_wyt[cbase + upair * 8 + 2 * lq + 1];
                wG = g_wyt[cbase + 16 + upair * 8 + 2 * lq];
                wO = g_wyt[cbase + 16 + upair * 8 + 2 * lq + 1];
            }
            int niI = g32 * 4 + upair;      // i/f accumulator
            int niG = g32 * 4 + 2 + upair;  // g/o accumulator
#pragma unroll
            for (int mi = 0; mi < 2; ++mi) {
#pragma unroll
                for (int half = 0; half < 2; ++half) {
                    int gb = row0 + wm * 32 + mi * 16 + half * 8 + lr;
                    float gi = acc[mi][niI][half * 2 + 0] + bI;
                    float gf = acc[mi][niI][half * 2 + 1] + bF;
                    float gg = acc[mi][niG][half * 2 + 0] + bG;
                    float go = acc[mi][niG][half * 2 + 1] + bO;
                    float cold;
                    if (MODE == 0) {
                        cold = cin[gb * HE + unit];
                    } else {
                        float yv = __half2float(g_yt16[gb]);
                        gi += yv * wI; gf += yv * wF; gg += yv * wG; go += yv * wO;
                        cold = dcin[gb * 512 + 256 + unit];
                    }
                    float c2 = sigf(gf) * cold + sigf(gi) * ftanh(gg);
                    float h2 = sigf(go) * ftanh(c2);
                    if (MODE == 0) {
                        h16out[gb * HE + unit] = __float2half_rn(h2);
                        cout[gb * HE + unit] = c2;
                        g_Xenc16[((size_t)gb * T + t) * HE + unit] = __float2half_rn(h2);
                    } else {
                        dcout[gb * 512 + unit] = h2;
                        dcout[gb * 512 + 256 + unit] = c2;
                        d16out[gb * 512 + unit] = __float2half_rn(h2);
                        d16out[gb * 512 + 256 + unit] = __float2half_rn(c2);
                    }
                }
            }
        }
    }
}

// ---------------- fp16 plain GEMM, N=256 (xenc_proj and q) ----------------
// mode 0: xproj16 = Xenc @ Wxp + da1b  (M = B*T, K = 256), fp16 out
// mode 1: q       = [d|c] @ Wq         (M = B,   K = 512), fp32 out
__global__ __launch_bounds__(256) void gemm256_mma_kernel(int mode, int pin,
                                                          const float* __restrict__ bias) {
    const __half* Aptr;
    const __half* Wptr;
    int lda, NC;
    if (mode == 0) { Aptr = g_Xenc16;    Wptr = g_Wxp16; lda = 256; NC = 8; }
    else           { Aptr = g_dc16[pin]; Wptr = g_Wq16;  lda = 512; NC = 16; }

    __shared__ __align__(16) unsigned Asw[2][2 * AG];
    __shared__ __align__(16) unsigned Bsw[2][2 * BG2];

    int tid = threadIdx.x;
    int lane = tid & 31;
    int wid = tid >> 5;
    int wm = wid & 3, wn = wid >> 2;
    int lq = lane & 3, lr = lane >> 2;
    int row0 = blockIdx.x * BM;
    int col0 = blockIdx.y * 64;
    int cg = col0 >> 6;

    int arow = tid >> 1;
    int akf = tid & 1;
    int rt = arow & 15, mt = arow >> 4;
    int r = rt & 7, rhalf = rt >> 3;
    int abase = akf * AG + mt * 128 + rhalf;
    const __half* arowp = Aptr + (size_t)(row0 + arow) * lda + akf * 16;
    const int2* wp = reinterpret_cast<const int2*>(Wptr);

    float acc[2][4][4] = {};
    int4 av0, av1;
    int2 bv0, bv1;

    auto loadChunk = [&](int kc) {
        const __half* p = arowp + kc * 32;
        av0 = *(const int4*)p;
        av1 = *(const int4*)(p + 8);
        bv0 = wp[(((size_t)(kc * 2 + 0) * 4 + cg) << 8) + tid];
        bv1 = wp[(((size_t)(kc * 2 + 1) * 4 + cg) << 8) + tid];
    };
    auto storeChunk = [&](int buf) {
        unsigned v[8] = {(unsigned)av0.x, (unsigned)av0.y, (unsigned)av0.z, (unsigned)av0.w,
                         (unsigned)av1.x, (unsigned)av1.y, (unsigned)av1.z, (unsigned)av1.w};
        unsigned* as = Asw[buf] + abase;
#pragma unroll
        for (int q4 = 0; q4 < 2; ++q4)
#pragma unroll
            for (int j2 = 0; j2 < 4; ++j2)
                as[((r * 4 + (j2 ^ (r >> 1))) << 2) + q4 * 2] = v[q4 * 4 + j2];
        *(int2*)&Bsw[buf][tid * 2] = bv0;
        *(int2*)&Bsw[buf][BG2 + tid * 2] = bv1;
    };
    auto compute = [&](int buf) {
        int aoff = (lr * 4 + (lq ^ (lr >> 1))) * 4;
#pragma unroll
        for (int kf2 = 0; kf2 < 2; ++kf2) {
            const unsigned* as = &Asw[buf][kf2 * AG];
            const unsigned* bs = &Bsw[buf][kf2 * BG2];
            int4 af[2];
            int2 bf[4];
#pragma unroll
            for (int mi = 0; mi < 2; ++mi)
                af[mi] = *(const int4*)&as[(wm * 2 + mi) * 128 + aoff];
#pragma unroll
            for (int ni = 0; ni < 4; ++ni)
                bf[ni] = *(const int2*)&bs[(wn * 4 + ni) * 64 + lane * 2];
#pragma unroll
            for (int mi = 0; mi < 2; ++mi)
#pragma unroll
                for (int ni = 0; ni < 4; ++ni)
                    mma_f16(acc[mi][ni], af[mi], bf[ni]);
        }
    };

    loadChunk(0);
    storeChunk(0);
    __syncthreads();
#pragma unroll 1
    for (int kc = 0; kc < NC; ++kc) {
        int cur = kc & 1;
        if (kc + 1 < NC) loadChunk(kc + 1);
        compute(cur);
        if (kc + 1 < NC) storeChunk(cur ^ 1);
        __syncthreads();
    }

#pragma unroll
    for (int mi = 0; mi < 2; ++mi) {
#pragma unroll
        for (int half = 0; half < 2; ++half) {
            int gb = row0 + wm * 32 + mi * 16 + half * 8 + lr;
#pragma unroll
            for (int ni = 0; ni < 4; ++ni) {
                int col = col0 + wn * 32 + ni * 8 + 2 * lq;
                float v0 = acc[mi][ni][half * 2 + 0] + (bias ? bias[col] : 0.f);
                float v1 = acc[mi][ni][half * 2 + 1] + (bias ? bias[col + 1] : 0.f);
                if (mode == 0) {
                    __half2 hv = __floats2half2_rn(v0, v1);
                    *(__half2*)&g_xproj16[(size_t)gb * HE + col] = hv;
                } else {
                    *(float2*)&g_q[(size_t)gb * HE + col] = make_float2(v0, v1);
                }
            }
        }
    }
}

// ---------------- decoder attention (row-wise fused, fp16 streams) --------
__global__ __launch_bounds__(256) void dec_attn_kernel(const float* __restrict__ yprev,
                                                       const float* __restrict__ a2w,
                                                       const float* __restrict__ a2b,
                                                       const float* __restrict__ fcw,
                                                       const float* __restrict__ fcb, int t) {
    int b = blockIdx.x;
    int h = threadIdx.x;
    float qh = g_q[b * HE + h];
    float w = a2w[h];
    const __half* xp = g_xproj16 + (size_t)(b * T) * HE + h;
    float sloc[T];
#pragma unroll
    for (int tt = 0; tt < T; ++tt)
        sloc[tt] = ftanh(__half2float(xp[tt * HE]) + qh) * w;

    __shared__ float part[8][T];
    __shared__ float scbuf[T];
    __shared__ float beta[T];
    int lane = h & 31, wid = h >> 5;
#pragma unroll
    for (int tt = 0; tt < T; ++tt) {
        float v = sloc[tt];
        for (int o = 16; o > 0; o >>= 1) v += __shfl_down_sync(0xFFFFFFFFu, v, o);
        if (!lane) part[wid][tt] = v;
    }
    __syncthreads();
    if (h < T) {
        float s = a2b[0];
#pragma unroll
        for (int w8 = 0; w8 < 8; ++w8) s += part[w8][h];
        scbuf[h] = s;
    }
    __syncthreads();
    if (h < T) {
        float mx = -1e30f;
#pragma unroll
        for (int tt = 0; tt < T; ++tt) mx = fmaxf(mx, scbuf[tt]);
        float sum = 0.f;
#pragma unroll
        for (int tt = 0; tt < T; ++tt) sum += __expf(scbuf[tt] - mx);
        beta[h] = __expf(scbuf[h] - mx) * __fdividef(1.f, sum);
    }
    __syncthreads();
    const __half* xe = g_Xenc16 + (size_t)(b * T) * HE + h;
    float ctx = 0.f;
#pragma unroll
    for (int tt = 0; tt < T; ++tt) ctx += beta[tt] * __half2float(xe[tt * HE]);
    g_ctx[b * HE + h] = ctx;
    float yv = ctx * fcw[h];
    for (int o = 16; o > 0; o >>= 1) yv += __shfl_down_sync(0xFFFFFFFFu, yv, o);
    __syncthreads();
    if (!lane) part[wid][0] = yv;
    __syncthreads();
    if (h == 0) {
        float s = 0.f;
#pragma unroll
        for (int w8 = 0; w8 < 8; ++w8) s += part[w8][0];
        g_yt16[b] = __float2half_rn(s + yprev[b * T + t] * fcw[HE] + fcb[0]);
    }
}

// ---------------- final output --------------------------------------------
__global__ void final_kernel(const float* __restrict__ ffw, const float* __restrict__ ffb,
                             float* __restrict__ out, int pin) {
    int gtid = blockIdx.x * blockDim.x + threadIdx.x;
    int warp = gtid >> 5;
    int lane = gtid & 31;
    if (warp >= B) return;
    const float* d = g_dc[pin] + warp * 512;
    const float* ctx = g_ctx + warp * HE;
    float s = 0.f;
    for (int h = lane; h < HE; h += 32) s += d[h] * ffw[h] + ctx[h] * ffw[HE + h];
    for (int o = 16; o > 0; o >>= 1) s += __shfl_down_sync(0xFFFFFFFFu, s, o);
    if (!lane) out[warp] = s + ffb[0];
}

// ---------------- launch ---------------------------------------------------
extern "C" void kernel_launch(void* const* d_in, const int* in_sizes, int n_in,
                              void* d_out, int out_size) {
    const float* X      = (const float*)d_in[0];
    const float* yprev  = (const float*)d_in[1];
    const float* e1w    = (const float*)d_in[2];
    const float* e1b    = (const float*)d_in[3];
    const float* e2w    = (const float*)d_in[4];
    const float* e2b    = (const float*)d_in[5];
    const float* l2_wih = (const float*)d_in[9];
    const float* l2_whh = (const float*)d_in[10];
    const float* l2_b   = (const float*)d_in[11];
    const float* da1w   = (const float*)d_in[12];
    const float* da1b   = (const float*)d_in[13];
    const float* da2w   = (const float*)d_in[14];
    const float* da2b   = (const float*)d_in[15];
    const float* dlwih  = (const float*)d_in[16];
    const float* dlwhh  = (const float*)d_in[17];
    const float* dlb    = (const float*)d_in[18];
    const float* fcw    = (const float*)d_in[19];
    const float* fcb    = (const float*)d_in[20];
    const float* ffw    = (const float*)d_in[21];
    const float* ffb    = (const float*)d_in[22];
    float* out = (float*)d_out;

    pack_kernel<<<512, 256>>>(l2_wih, l2_whh, l2_b, dlwih, dlwhh, dlb, da1w);
    init_kernel<<<512, 256>>>();
    attn_kernel<<<B, 128>>>(X, yprev, e1w, e1b, e2w, e2b);

    for (int t = 0; t < T; ++t)
        lstm_mma_kernel<0><<<dim3(B / BM, NG / BN), 256>>>(t, t & 1, (t + 1) & 1);

    // xenc_proj over all (b, t)
    gemm256_mma_kernel<<<dim3(B * T / BM, HE / 64), 256>>>(0, 0, da1b);

    for (int t = 0; t < T; ++t) {
        gemm256_mma_kernel<<<dim3(B / BM, HE / 64), 256>>>(1, t & 1, nullptr);
        dec_attn_kernel<<<B, 256>>>(yprev, da2w, da2b, fcw, fcb, t);
        lstm_mma_kernel<1><<<dim3(B / BM, NG / BN), 256>>>(0, t & 1, (t + 1) & 1);
    }

    final_kernel<<<B * 32 / 256, 256>>>(ffw, ffb, out, T & 1);
}